// round 8
// baseline (speedup 1.0000x reference)
#include <cuda_runtime.h>
#include <cstdint>

// ============================================================================
// MemristorLinear: out[B,OUT] = x[B,IN] @ W[OUT,IN]^T + bias,
//                  W[o,i] = values[w_idx[o,i]]
// B=8192, IN=4096, OUT=4096, NVAL=1024.
//
// R8: tf32 HMMA measured rate-capped (~177 TF/s, tensor% flat at 57 across
// occupancies). Switch to int8 IMMA m16n8k32 (4x MACs/instr) with 2-level
// quantization:  x ~ (p1 + p2/128)/Sx,  w ~ (q1 + q2/128)/Sw  (int8 p,q),
// 3 products on 2 int32 accumulators (drop p2*q2):
//   acc1 += p1*q1 ;  acc2 += p1*q2 + p2*q1
//   out = (acc1 + acc2/128) / (Sx*Sw) + bias
// Codebook (1024 vals) quantized once; gather writes int8 pairs.
// ============================================================================

#define B_DIM   8192
#define IN_DIM  4096
#define OUT_DIM 4096

#define BM 128
#define BN 128
#define BK 64
#define STAGES 3
#define KITERS (IN_DIM / BK)       // 64
#define THREADS 256

#define ROWB 80                          // smem bytes per row (64 data +16 pad)
#define PLANE_BYTES (128 * ROWB)         // 10240
#define STAGE_BYTES (4 * PLANE_BYTES)    // 40960 (A1,A2,B1,B2)
#define SMEM_BYTES  (STAGES * STAGE_BYTES)  // 122880

#define SXQ 15.875f                      // 127/8
#define SWQ 25.4f                        // 127/5
// 1/(SXQ*SWQ) = 40/16129
#define INV_S (40.0f / 16129.0f)

// Scratch (allocation-free rule: __device__ globals)
__device__ char g_X1[(size_t)B_DIM * IN_DIM];
__device__ char g_X2[(size_t)B_DIM * IN_DIM];
__device__ char g_W1[(size_t)OUT_DIM * IN_DIM];
__device__ char g_W2[(size_t)OUT_DIM * IN_DIM];
__device__ signed char g_q1v[1024];
__device__ signed char g_q2v[1024];
__device__ int g_idx_is64;

// ---------------------------------------------------------------------------
// helpers
// ---------------------------------------------------------------------------
__device__ __forceinline__ uint32_t smem_u32(const void* p) {
    uint32_t a;
    asm("{ .reg .u64 t; cvta.to.shared.u64 t, %1; cvt.u32.u64 %0, t; }"
        : "=r"(a) : "l"(p));
    return a;
}

__device__ __forceinline__ void cp_async16(uint32_t s, const void* g) {
    asm volatile("cp.async.cg.shared.global [%0], [%1], 16;\n" :: "r"(s), "l"(g));
}

// D += A*B : m16n8k32 s8 x s8 -> s32
__device__ __forceinline__ void mma_s8(int* c, const uint32_t* a,
                                       const uint32_t* b) {
    asm volatile(
        "mma.sync.aligned.m16n8k32.row.col.s32.s8.s8.s32 "
        "{%0,%1,%2,%3}, {%4,%5,%6,%7}, {%8,%9}, {%0,%1,%2,%3};"
        : "+r"(c[0]), "+r"(c[1]), "+r"(c[2]), "+r"(c[3])
        : "r"(a[0]), "r"(a[1]), "r"(a[2]), "r"(a[3]), "r"(b[0]), "r"(b[1]));
}

// 2-level int8 quantization: v*scale ~ hi + lo/128
__device__ __forceinline__ void quant2(float v, float scale,
                                       signed char& hi, signed char& lo) {
    float s  = v * scale;
    float p1 = rintf(s);
    p1 = fminf(fmaxf(p1, -127.0f), 127.0f);
    float p2 = rintf((s - p1) * 128.0f);
    p2 = fminf(fmaxf(p2, -127.0f), 127.0f);
    hi = (signed char)(int)p1;
    lo = (signed char)(int)p2;
}

// ---------------------------------------------------------------------------
// Pre-pass 0: detect w_idx dtype (indices < 1024 -> int64 odd words all 0)
// ---------------------------------------------------------------------------
__global__ void mml_detect_idx(const int* __restrict__ w32) {
    int nz = 0;
    #pragma unroll
    for (int i = 0; i < 64; i++) nz |= w32[2 * i + 1];
    g_idx_is64 = (nz == 0) ? 1 : 0;
}

// ---------------------------------------------------------------------------
// Pre-pass 1: quantize the 1024-entry codebook
// ---------------------------------------------------------------------------
__global__ void mml_quant_vals(const float* __restrict__ values) {
    int t = threadIdx.x;
    signed char hi, lo;
    quant2(values[t], SWQ, hi, lo);
    g_q1v[t] = hi;
    g_q2v[t] = lo;
}

// ---------------------------------------------------------------------------
// Pre-pass 2: quantize x into int8 planes g_X1/g_X2
// ---------------------------------------------------------------------------
__global__ void mml_quant_x(const float4* __restrict__ x, int n4) {
    int t = blockIdx.x * blockDim.x + threadIdx.x;
    if (t >= n4) return;
    float4 v = x[t];
    char4 a, b;
    quant2(v.x, SXQ, (signed char&)a.x, (signed char&)b.x);
    quant2(v.y, SXQ, (signed char&)a.y, (signed char&)b.y);
    quant2(v.z, SXQ, (signed char&)a.z, (signed char&)b.z);
    quant2(v.w, SXQ, (signed char&)a.w, (signed char&)b.w);
    reinterpret_cast<char4*>(g_X1)[t] = a;
    reinterpret_cast<char4*>(g_X2)[t] = b;
}

// ---------------------------------------------------------------------------
// Pre-pass 3: gather quantized W planes from the codebook
// ---------------------------------------------------------------------------
__global__ void mml_gather_w(const void* __restrict__ widx, int n4) {
    __shared__ signed char s1[1024], s2[1024];
    for (int i = threadIdx.x; i < 1024; i += blockDim.x) {
        s1[i] = g_q1v[i];
        s2[i] = g_q2v[i];
    }
    __syncthreads();
    int t = blockIdx.x * blockDim.x + threadIdx.x;
    if (t >= n4) return;
    int i0, i1, i2, i3;
    if (g_idx_is64) {
        const longlong2* p = reinterpret_cast<const longlong2*>(widx) + 2 * t;
        longlong2 a = p[0];
        longlong2 b = p[1];
        i0 = (int)a.x; i1 = (int)a.y; i2 = (int)b.x; i3 = (int)b.y;
    } else {
        int4 a = reinterpret_cast<const int4*>(widx)[t];
        i0 = a.x; i1 = a.y; i2 = a.z; i3 = a.w;
    }
    char4 a, b;
    a.x = s1[i0]; a.y = s1[i1]; a.z = s1[i2]; a.w = s1[i3];
    b.x = s2[i0]; b.y = s2[i1]; b.z = s2[i2]; b.w = s2[i3];
    reinterpret_cast<char4*>(g_W1)[t] = a;
    reinterpret_cast<char4*>(g_W2)[t] = b;
}

// ---------------------------------------------------------------------------
// Main GEMM: 128x128 CTA tile, 8 warps (2 M x 4 N), 64x32 warp tiles,
// int8 IMMA m16n8k32, BK=64 (2 k-chunks per stage).
// ---------------------------------------------------------------------------
__global__ __launch_bounds__(THREADS, 1)
void mml_gemm(const float* __restrict__ bias, float* __restrict__ out) {
    extern __shared__ char sm[];
    const int tid  = threadIdx.x;
    const int lane = tid & 31;
    const int wid  = tid >> 5;
    const int wm   = wid & 1;        // 2 warps in M
    const int wn   = wid >> 1;       // 4 warps in N
    const int m0   = blockIdx.y * BM;
    const int n0   = blockIdx.x * BN;

    const uint32_t smem_base = smem_u32(sm);
    const int lr = lane >> 2;        // 0..7
    const int lc = lane & 3;         // 0..3

    int acc1[4][4][4], acc2[4][4][4];
    #pragma unroll
    for (int mt = 0; mt < 4; mt++)
        #pragma unroll
        for (int nt = 0; nt < 4; nt++)
            #pragma unroll
            for (int r = 0; r < 4; r++) { acc1[mt][nt][r] = 0; acc2[mt][nt][r] = 0; }

    // ---- stage loader: 4 planes (A1,A2,B1,B2), 128 rows x 64B each ----
    auto load_stage = [&](int ks, int slot) {
        uint32_t base = smem_base + (uint32_t)(slot * STAGE_BYTES);
        const char* gp[4];
        gp[0] = g_X1 + (size_t)m0 * IN_DIM + (size_t)ks * BK;
        gp[1] = g_X2 + (size_t)m0 * IN_DIM + (size_t)ks * BK;
        gp[2] = g_W1 + (size_t)n0 * IN_DIM + (size_t)ks * BK;
        gp[3] = g_W2 + (size_t)n0 * IN_DIM + (size_t)ks * BK;
        #pragma unroll
        for (int p = 0; p < 4; p++) {
            #pragma unroll
            for (int q = tid; q < 512; q += THREADS) {     // 128 rows x 4 chunks
                int row = q >> 2, ch = q & 3;
                cp_async16(base + (uint32_t)(p * PLANE_BYTES + row * ROWB + ch * 16),
                           gp[p] + (size_t)row * IN_DIM + ch * 16);
            }
        }
    };

    load_stage(0, 0);
    asm volatile("cp.async.commit_group;" ::: "memory");
    load_stage(1, 1);
    asm volatile("cp.async.commit_group;" ::: "memory");

    for (int i = 0; i < KITERS; i++) {
        asm volatile("cp.async.wait_group 1;" ::: "memory");
        __syncthreads();

        if (i + 2 < KITERS) load_stage(i + 2, (i + 2) % STAGES);
        asm volatile("cp.async.commit_group;" ::: "memory");

        const char* sA1 = sm + (i % STAGES) * STAGE_BYTES;
        const char* sA2 = sA1 + PLANE_BYTES;
        const char* sB1 = sA2 + PLANE_BYTES;
        const char* sB2 = sB1 + PLANE_BYTES;

        #pragma unroll
        for (int kc = 0; kc < 2; kc++) {
            const int ko = kc * 32 + lc * 4;
            uint32_t a1[4][4], a2[4][4], b1[4][2], b2[4][2];
            #pragma unroll
            for (int mt = 0; mt < 4; mt++) {
                int row = wm * 64 + mt * 16 + lr;
                int o0 = row * ROWB + ko;
                int o1 = o0 + 8 * ROWB;
                a1[mt][0] = *(const uint32_t*)(sA1 + o0);
                a1[mt][1] = *(const uint32_t*)(sA1 + o1);
                a1[mt][2] = *(const uint32_t*)(sA1 + o0 + 16);
                a1[mt][3] = *(const uint32_t*)(sA1 + o1 + 16);
                a2[mt][0] = *(const uint32_t*)(sA2 + o0);
                a2[mt][1] = *(const uint32_t*)(sA2 + o1);
                a2[mt][2] = *(const uint32_t*)(sA2 + o0 + 16);
                a2[mt][3] = *(const uint32_t*)(sA2 + o1 + 16);
            }
            #pragma unroll
            for (int nt = 0; nt < 4; nt++) {
                int nrow = wn * 32 + nt * 8 + lr;
                int ob = nrow * ROWB + ko;
                b1[nt][0] = *(const uint32_t*)(sB1 + ob);
                b1[nt][1] = *(const uint32_t*)(sB1 + ob + 16);
                b2[nt][0] = *(const uint32_t*)(sB2 + ob);
                b2[nt][1] = *(const uint32_t*)(sB2 + ob + 16);
            }
            #pragma unroll
            for (int mt = 0; mt < 4; mt++)
                #pragma unroll
                for (int nt = 0; nt < 4; nt++) {
                    mma_s8(acc1[mt][nt], a1[mt], b1[nt]);
                    mma_s8(acc2[mt][nt], a1[mt], b2[nt]);
                    mma_s8(acc2[mt][nt], a2[mt], b1[nt]);
                }
        }
    }

    // ---- epilogue: combine scales, add bias, write float2 coalesced ----
    float2 bb[4];
    #pragma unroll
    for (int nt = 0; nt < 4; nt++) {
        int cn = n0 + wn * 32 + nt * 8 + lc * 2;
        bb[nt].x = __ldg(bias + cn);
        bb[nt].y = __ldg(bias + cn + 1);
    }
    const float k128 = 1.0f / 128.0f;
    #pragma unroll
    for (int mt = 0; mt < 4; mt++) {
        int r0 = m0 + wm * 64 + mt * 16 + lr;
        int r1 = r0 + 8;
        float* o0 = out + (size_t)r0 * OUT_DIM;
        float* o1 = out + (size_t)r1 * OUT_DIM;
        #pragma unroll
        for (int nt = 0; nt < 4; nt++) {
            int cn = n0 + wn * 32 + nt * 8 + lc * 2;
            float2 v0, v1;
            v0.x = fmaf(__int2float_rn(acc2[mt][nt][0]), k128,
                        __int2float_rn(acc1[mt][nt][0])) * INV_S + bb[nt].x;
            v0.y = fmaf(__int2float_rn(acc2[mt][nt][1]), k128,
                        __int2float_rn(acc1[mt][nt][1])) * INV_S + bb[nt].y;
            v1.x = fmaf(__int2float_rn(acc2[mt][nt][2]), k128,
                        __int2float_rn(acc1[mt][nt][2])) * INV_S + bb[nt].x;
            v1.y = fmaf(__int2float_rn(acc2[mt][nt][3]), k128,
                        __int2float_rn(acc1[mt][nt][3])) * INV_S + bb[nt].y;
            *reinterpret_cast<float2*>(o0 + cn) = v0;
            *reinterpret_cast<float2*>(o1 + cn) = v1;
        }
    }
}

// ---------------------------------------------------------------------------
// kernel_launch — inputs identified by element count (order-proof):
//   x: 33554432, values: 1024, bias: 4096, w_idx: 16777216
// ---------------------------------------------------------------------------
extern "C" void kernel_launch(void* const* d_in, const int* in_sizes, int n_in,
                              void* d_out, int out_size) {
    const float* x      = nullptr;
    const float* values = nullptr;
    const float* bias   = nullptr;
    const void*  widx   = nullptr;

    for (int i = 0; i < n_in; i++) {
        switch (in_sizes[i]) {
            case 33554432: x      = (const float*)d_in[i]; break;
            case 1024:     values = (const float*)d_in[i]; break;
            case 4096:     bias   = (const float*)d_in[i]; break;
            case 16777216: widx   = d_in[i];               break;
            default: break;
        }
    }
    float* out = (float*)d_out;

    int nx4 = (B_DIM * IN_DIM) / 4;        // 8388608
    int nw4 = (OUT_DIM * IN_DIM) / 4;      // 4194304

    mml_detect_idx<<<1, 1>>>((const int*)widx);
    mml_quant_vals<<<1, 1024>>>(values);
    mml_quant_x<<<nx4 / 256, 256>>>((const float4*)x, nx4);
    mml_gather_w<<<nw4 / 256, 256>>>(widx, nw4);

    cudaFuncSetAttribute(mml_gemm, cudaFuncAttributeMaxDynamicSharedMemorySize,
                         SMEM_BYTES);
    dim3 grid(OUT_DIM / BN, B_DIM / BM);   // (32, 64)
    mml_gemm<<<grid, THREADS, SMEM_BYTES>>>(bias, out);
}

// round 9
// speedup vs baseline: 3.2699x; 3.2699x over previous
#include <cuda_runtime.h>
#include <cstdint>

// ============================================================================
// MemristorLinear: out[B,OUT] = x[B,IN] @ W[OUT,IN]^T + bias,
//                  W[o,i] = values[w_idx[o,i]]
// B=8192, IN=4096, OUT=4096, NVAL=1024.
//
// R9: IMMA measured slow on sm_103a legacy pipe -> revert to tf32
// mma.sync.m16n8k8 (R7 mainloop). Attack the constant ~1400cyc/iter
// barrier/loop overhead by halving iterations: BK=64 (KITERS=64),
// 3-stage cp.async, CTA 128x128, 8 warps (2Mx4N, 64x32 warp tiles).
// ============================================================================

#define B_DIM   8192
#define IN_DIM  4096
#define OUT_DIM 4096

#define BM 128
#define BN 128
#define BK 64
#define STAGES 3
#define KITERS (IN_DIM / BK)     // 64
#define THREADS 256

#define LDSTRIDE 68                        // floats per smem row (64 + 4 pad)
#define A_FLOATS (BM * LDSTRIDE)           // 8704
#define B_FLOATS (BN * LDSTRIDE)           // 8704
#define STAGE_FLOATS (A_FLOATS + B_FLOATS) // 17408
#define SMEM_BYTES (STAGES * STAGE_FLOATS * 4)  // 208896 (204 KB, 1 CTA/SM)

// Scratch (allocation-free rule: __device__ globals)
__device__ float g_W[(size_t)OUT_DIM * IN_DIM];   // 64 MB tf32-rounded gathered W
__device__ float g_X[(size_t)B_DIM * IN_DIM];     // 128 MB tf32-rounded x
__device__ int   g_idx_is64;                      // w_idx dtype flag

// ---------------------------------------------------------------------------
// helpers
// ---------------------------------------------------------------------------
__device__ __forceinline__ uint32_t smem_u32(const void* p) {
    uint32_t a;
    asm("{ .reg .u64 t; cvta.to.shared.u64 t, %1; cvt.u32.u64 %0, t; }"
        : "=r"(a) : "l"(p));
    return a;
}

__device__ __forceinline__ void cp_async16(uint32_t s, const void* g) {
    asm volatile("cp.async.cg.shared.global [%0], [%1], 16;\n" :: "r"(s), "l"(g));
}

__device__ __forceinline__ uint32_t tf32_rna(float f) {
    uint32_t u;
    asm("cvt.rna.tf32.f32 %0, %1;" : "=r"(u) : "f"(f));
    return u;
}

// D += A*B : m16n8k8 tf32, row.col, fp32 accumulate
__device__ __forceinline__ void mma_tf32(float* c, const uint32_t* a,
                                         const uint32_t* b) {
    asm volatile(
        "mma.sync.aligned.m16n8k8.row.col.f32.tf32.tf32.f32 "
        "{%0,%1,%2,%3}, {%4,%5,%6,%7}, {%8,%9}, {%0,%1,%2,%3};"
        : "+f"(c[0]), "+f"(c[1]), "+f"(c[2]), "+f"(c[3])
        : "r"(a[0]), "r"(a[1]), "r"(a[2]), "r"(a[3]), "r"(b[0]), "r"(b[1]));
}

// ---------------------------------------------------------------------------
// Pre-pass 0: detect w_idx dtype (indices < 1024 -> int64 odd words all 0)
// ---------------------------------------------------------------------------
__global__ void mml_detect_idx(const int* __restrict__ w32) {
    int nz = 0;
    #pragma unroll
    for (int i = 0; i < 64; i++) nz |= w32[2 * i + 1];
    g_idx_is64 = (nz == 0) ? 1 : 0;
}

// ---------------------------------------------------------------------------
// Pre-pass 1: round x to tf32 into g_X
// ---------------------------------------------------------------------------
__global__ void mml_round_x(const float4* __restrict__ x, int n4) {
    int t = blockIdx.x * blockDim.x + threadIdx.x;
    if (t < n4) {
        float4 v = x[t];
        uint4 o;
        o.x = tf32_rna(v.x); o.y = tf32_rna(v.y);
        o.z = tf32_rna(v.z); o.w = tf32_rna(v.w);
        reinterpret_cast<uint4*>(g_X)[t] = o;
    }
}

// ---------------------------------------------------------------------------
// Pre-pass 2: gather W from codebook (int32 OR int64 idx), tf32-round to g_W
// ---------------------------------------------------------------------------
__global__ void mml_gather_w(const float* __restrict__ values,
                             const void* __restrict__ widx, int n4) {
    int t = blockIdx.x * blockDim.x + threadIdx.x;
    if (t >= n4) return;
    int i0, i1, i2, i3;
    if (g_idx_is64) {
        const longlong2* p = reinterpret_cast<const longlong2*>(widx) + 2 * t;
        longlong2 a = p[0];
        longlong2 b = p[1];
        i0 = (int)a.x; i1 = (int)a.y; i2 = (int)b.x; i3 = (int)b.y;
    } else {
        int4 a = reinterpret_cast<const int4*>(widx)[t];
        i0 = a.x; i1 = a.y; i2 = a.z; i3 = a.w;
    }
    uint4 o;
    o.x = tf32_rna(__ldg(values + i0));
    o.y = tf32_rna(__ldg(values + i1));
    o.z = tf32_rna(__ldg(values + i2));
    o.w = tf32_rna(__ldg(values + i3));
    reinterpret_cast<uint4*>(g_W)[t] = o;
}

// ---------------------------------------------------------------------------
// Main GEMM: 128x128 CTA tile, 8 warps (2 M x 4 N), 64x32 warp tiles, BK=64
// ---------------------------------------------------------------------------
__global__ __launch_bounds__(THREADS, 1)
void mml_gemm(const float* __restrict__ bias, float* __restrict__ out) {
    extern __shared__ float sm[];
    const int tid  = threadIdx.x;
    const int lane = tid & 31;
    const int wid  = tid >> 5;
    const int wm   = wid & 1;        // 2 warps in M
    const int wn   = wid >> 1;       // 4 warps in N
    const int m0   = blockIdx.y * BM;
    const int n0   = blockIdx.x * BN;

    const uint32_t smem_base = smem_u32(sm);
    const int lr = lane >> 2;        // 0..7
    const int lc = lane & 3;         // 0..3

    // accumulators: 4 m-tiles x 4 n-tiles x 4 regs = 64
    float c[4][4][4];
    #pragma unroll
    for (int mt = 0; mt < 4; mt++)
        #pragma unroll
        for (int nt = 0; nt < 4; nt++)
            #pragma unroll
            for (int r = 0; r < 4; r++) c[mt][nt][r] = 0.0f;

    // ---- stage loader: A (BMxBK) + B (BNxBK) via cp.async, padded rows ----
    // 64 floats per row = 16 x 16B chunks; 128 rows -> 2048 chunks per matrix.
    auto load_stage = [&](int ks, int slot) {
        uint32_t sa = smem_base + (uint32_t)(slot * STAGE_FLOATS * 4);
        uint32_t sb = sa + A_FLOATS * 4;
        const float* ag = g_X + (size_t)m0 * IN_DIM + (size_t)ks * BK;
        const float* bg = g_W + (size_t)n0 * IN_DIM + (size_t)ks * BK;
        #pragma unroll
        for (int q = tid; q < BM * 16; q += THREADS) {
            int row = q >> 4, kc = q & 15;
            cp_async16(sa + (uint32_t)(row * LDSTRIDE + kc * 4) * 4,
                       ag + (size_t)row * IN_DIM + kc * 4);
        }
        #pragma unroll
        for (int q = tid; q < BN * 16; q += THREADS) {
            int row = q >> 4, kc = q & 15;
            cp_async16(sb + (uint32_t)(row * LDSTRIDE + kc * 4) * 4,
                       bg + (size_t)row * IN_DIM + kc * 4);
        }
    };

    load_stage(0, 0);
    asm volatile("cp.async.commit_group;" ::: "memory");
    load_stage(1, 1);
    asm volatile("cp.async.commit_group;" ::: "memory");

    for (int i = 0; i < KITERS; i++) {
        asm volatile("cp.async.wait_group 1;" ::: "memory");
        __syncthreads();

        if (i + 2 < KITERS) load_stage(i + 2, (i + 2) % STAGES);
        asm volatile("cp.async.commit_group;" ::: "memory");

        const float* sA = sm + (i % STAGES) * STAGE_FLOATS;
        const float* sB = sA + A_FLOATS;

        #pragma unroll
        for (int kk = 0; kk < 8; kk++) {
            const int k0 = kk * 8 + lc;
            uint32_t af[4][4], bf[4][2];
            #pragma unroll
            for (int mt = 0; mt < 4; mt++) {
                int row = wm * 64 + mt * 16 + lr;
                const uint32_t* p0 = (const uint32_t*)(sA + row * LDSTRIDE);
                const uint32_t* p1 = (const uint32_t*)(sA + (row + 8) * LDSTRIDE);
                af[mt][0] = p0[k0];
                af[mt][1] = p1[k0];
                af[mt][2] = p0[k0 + 4];
                af[mt][3] = p1[k0 + 4];
            }
            #pragma unroll
            for (int nt = 0; nt < 4; nt++) {
                int nrow = wn * 32 + nt * 8 + lr;
                const uint32_t* p = (const uint32_t*)(sB + nrow * LDSTRIDE);
                bf[nt][0] = p[k0];
                bf[nt][1] = p[k0 + 4];
            }
            #pragma unroll
            for (int mt = 0; mt < 4; mt++)
                #pragma unroll
                for (int nt = 0; nt < 4; nt++)
                    mma_tf32(c[mt][nt], af[mt], bf[nt]);
        }
    }

    // ---- epilogue: add bias, write float2 coalesced ----
    float2 bb[4];
    #pragma unroll
    for (int nt = 0; nt < 4; nt++) {
        int cn = n0 + wn * 32 + nt * 8 + lc * 2;
        bb[nt].x = __ldg(bias + cn);
        bb[nt].y = __ldg(bias + cn + 1);
    }
    #pragma unroll
    for (int mt = 0; mt < 4; mt++) {
        int r0 = m0 + wm * 64 + mt * 16 + lr;
        int r1 = r0 + 8;
        float* o0 = out + (size_t)r0 * OUT_DIM;
        float* o1 = out + (size_t)r1 * OUT_DIM;
        #pragma unroll
        for (int nt = 0; nt < 4; nt++) {
            int cn = n0 + wn * 32 + nt * 8 + lc * 2;
            float2 v0, v1;
            v0.x = c[mt][nt][0] + bb[nt].x;
            v0.y = c[mt][nt][1] + bb[nt].y;
            v1.x = c[mt][nt][2] + bb[nt].x;
            v1.y = c[mt][nt][3] + bb[nt].y;
            *reinterpret_cast<float2*>(o0 + cn) = v0;
            *reinterpret_cast<float2*>(o1 + cn) = v1;
        }
    }
}

// ---------------------------------------------------------------------------
// kernel_launch — inputs identified by element count (order-proof):
//   x: 33554432, values: 1024, bias: 4096, w_idx: 16777216
// ---------------------------------------------------------------------------
extern "C" void kernel_launch(void* const* d_in, const int* in_sizes, int n_in,
                              void* d_out, int out_size) {
    const float* x      = nullptr;
    const float* values = nullptr;
    const float* bias   = nullptr;
    const void*  widx   = nullptr;

    for (int i = 0; i < n_in; i++) {
        switch (in_sizes[i]) {
            case 33554432: x      = (const float*)d_in[i]; break;
            case 1024:     values = (const float*)d_in[i]; break;
            case 4096:     bias   = (const float*)d_in[i]; break;
            case 16777216: widx   = d_in[i];               break;
            default: break;
        }
    }
    float* out = (float*)d_out;

    int nx4 = (B_DIM * IN_DIM) / 4;        // 8388608
    int nw4 = (OUT_DIM * IN_DIM) / 4;      // 4194304

    mml_detect_idx<<<1, 1>>>((const int*)widx);
    mml_round_x<<<nx4 / 256, 256>>>((const float4*)x, nx4);
    mml_gather_w<<<nw4 / 256, 256>>>(values, widx, nw4);

    cudaFuncSetAttribute(mml_gemm, cudaFuncAttributeMaxDynamicSharedMemorySize,
                         SMEM_BYTES);
    dim3 grid(OUT_DIM / BN, B_DIM / BM);   // (32, 64)
    mml_gemm<<<grid, THREADS, SMEM_BYTES>>>(bias, out);
}